// round 1
// baseline (speedup 1.0000x reference)
#include <cuda_runtime.h>
#include <math.h>

// ---------------------------------------------------------------------------
// Problem constants
// ---------------------------------------------------------------------------
namespace {
constexpr int kB = 2, kS = 1024, kE = 1024, kH = 16, kD = 64, kF = 4096, kV = 32000;
constexpr int kBS  = kB * kS;   // 2048 tokens
constexpr int kBH  = kB * kH;   // 32 (b,h) pairs
constexpr int kQKV = 3 * kE;    // 3072 fused qkv cols
}

// ---------------------------------------------------------------------------
// Device scratch (allocation-free: static __device__ globals)
// ---------------------------------------------------------------------------
__device__ float g_emb [kBS * kE];
__device__ float g_hbuf[kBS * kE];
__device__ float g_qkv [kBS * kQKV];
__device__ float g_q   [kBH * kS * kD];
__device__ float g_kk  [kBH * kS * kD];
__device__ float g_vv  [kBH * kS * kD];
__device__ float g_sc  [(size_t)kBH * kS * kS];   // 128 MB attention scores
__device__ float g_o   [kBH * kS * kD];
__device__ float g_o2  [kBS * kE];
__device__ float g_u   [kBS * kF];
__device__ float g_g   [kBS * kF];
__device__ float g_wt  [kE * kQKV];               // transposed fused qkv weights
__device__ float g_ct  [kS * kD];                 // rope cos
__device__ float g_st  [kS * kD];                 // rope sin (sign folded)

// ---------------------------------------------------------------------------
// Generic tiled fp32 GEMM.
//   C[M,N] = alpha * A@B (+ C if ACCUM) (+ bias[n] if BIAS)
//   A row-major [M,K] lda;  B row-major [K,N] ldb  (or [N,K] if TRB -> C=A@B^T)
//   Batched via blockIdx.z with element strides sA/sB/sC.
//   CAUSAL: skip blocks entirely above the diagonal (scores GEMM).
// Requires: M%BM==0, N%BN==0, K%BK==0, all leading dims %4==0.
// ---------------------------------------------------------------------------
template<int BM,int BN,int BK,int TM,int TN,bool TRB,bool ACCUM,bool BIAS,bool CAUSAL>
__global__ void __launch_bounds__((BM/TM)*(BN/TN))
gemm_k(const float* __restrict__ A, int lda, long long sA,
       const float* __restrict__ B, int ldb, long long sB,
       float* __restrict__ C, int ldc, long long sC,
       const float* __restrict__ bias, float alpha, int K)
{
    constexpr int THREADS = (BM/TM)*(BN/TN);
    const int bx = blockIdx.x, by = blockIdx.y, bz = blockIdx.z;
    if (CAUSAL && bx * BN > by * BM + BM - 1) return;   // fully-masked tile

    A += (long long)bz * sA + (long long)by * BM * lda;
    C += (long long)bz * sC + (long long)by * BM * ldc + bx * BN;
    const float* Bb = B + (long long)bz * sB
                        + (TRB ? (long long)bx * BN * ldb : (long long)bx * BN);

    __shared__ float As[BK][BM];
    __shared__ float Bs[BK][BN];

    const int tid = threadIdx.x;
    const int tx  = tid % (BN / TN);
    const int ty  = tid / (BN / TN);

    float acc[TM][TN];
#pragma unroll
    for (int i = 0; i < TM; i++)
#pragma unroll
        for (int j = 0; j < TN; j++) acc[i][j] = 0.f;

    for (int kt = 0; kt < K; kt += BK) {
        // ---- A tile: BM x BK, transposed into As[k][m] ----
#pragma unroll
        for (int i = tid; i < BM * BK / 4; i += THREADS) {
            int m  = i / (BK / 4);
            int k4 = (i % (BK / 4)) * 4;
            float4 v = *reinterpret_cast<const float4*>(&A[(long long)m * lda + kt + k4]);
            As[k4 + 0][m] = v.x; As[k4 + 1][m] = v.y;
            As[k4 + 2][m] = v.z; As[k4 + 3][m] = v.w;
        }
        // ---- B tile ----
        if (!TRB) {
#pragma unroll
            for (int i = tid; i < BK * BN / 4; i += THREADS) {
                int k  = i / (BN / 4);
                int n4 = (i % (BN / 4)) * 4;
                *reinterpret_cast<float4*>(&Bs[k][n4]) =
                    *reinterpret_cast<const float4*>(&Bb[(long long)(kt + k) * ldb + n4]);
            }
        } else {
#pragma unroll
            for (int i = tid; i < BN * BK / 4; i += THREADS) {
                int n  = i / (BK / 4);
                int k4 = (i % (BK / 4)) * 4;
                float4 v = *reinterpret_cast<const float4*>(&Bb[(long long)n * ldb + kt + k4]);
                Bs[k4 + 0][n] = v.x; Bs[k4 + 1][n] = v.y;
                Bs[k4 + 2][n] = v.z; Bs[k4 + 3][n] = v.w;
            }
        }
        __syncthreads();

#pragma unroll
        for (int kk = 0; kk < BK; kk++) {
            float ra[TM], rb[TN];
#pragma unroll
            for (int i = 0; i < TM; i++) ra[i] = As[kk][ty * TM + i];
#pragma unroll
            for (int j = 0; j < TN; j++) rb[j] = Bs[kk][tx * TN + j];
#pragma unroll
            for (int i = 0; i < TM; i++)
#pragma unroll
                for (int j = 0; j < TN; j++) acc[i][j] += ra[i] * rb[j];
        }
        __syncthreads();
    }

#pragma unroll
    for (int i = 0; i < TM; i++) {
#pragma unroll
        for (int j = 0; j < TN; j++) {
            long long idx = (long long)(ty * TM + i) * ldc + tx * TN + j;
            float v = alpha * acc[i][j];
            if (BIAS)  v += bias[bx * BN + tx * TN + j];
            if (ACCUM) v += C[idx];
            C[idx] = v;
        }
    }
}

// ---------------------------------------------------------------------------
// Elementwise / helper kernels
// ---------------------------------------------------------------------------
__global__ void embed_k(const int* __restrict__ tok, const float* __restrict__ tab,
                        float* __restrict__ out)
{
    int idx = blockIdx.x * blockDim.x + threadIdx.x;   // kBS*kE threads
    int row = idx >> 10;      // /1024
    int e   = idx & 1023;
    out[idx] = tab[(size_t)tok[row] * kE + e];
}

__global__ void costab_k(float* __restrict__ ct, float* __restrict__ st)
{
    int idx = blockIdx.x * blockDim.x + threadIdx.x;   // kS*kD
    int s = idx / kD, i = idx % kD;
    float theta = powf(10000.f, (-2.f / (float)kD) * (float)(i & 31));
    float a = (float)s * theta;
    ct[idx] = cosf(a);
    st[idx] = sinf(a) * (i < kD / 2 ? -1.f : 1.f);
}

// fuse per-layer Wq/Wk/Wv [H,E,D] -> Wt [E, 3*H*D]
__global__ void wt_k(const float* __restrict__ wq, const float* __restrict__ wk,
                     const float* __restrict__ wv, float* __restrict__ wt)
{
    int idx = blockIdx.x * blockDim.x + threadIdx.x;   // kE*kQKV
    int e = idx / kQKV, c = idx % kQKV;
    int seg = c >> 10, cc = c & 1023;
    int h = cc >> 6, k = cc & 63;
    const float* w = (seg == 0) ? wq : (seg == 1) ? wk : wv;
    wt[idx] = w[((size_t)h * kE + e) * kD + k];
}

// qkv [BS, 3072] -> rope(q),rope(k),v in [B,H,S,D]
__global__ void rope_k(const float* __restrict__ qkv,
                       const float* __restrict__ ct, const float* __restrict__ st,
                       float* __restrict__ q, float* __restrict__ k, float* __restrict__ v)
{
    int idx = blockIdx.x * blockDim.x + threadIdx.x;   // kBS*kQKV
    int row = idx / kQKV, c = idx % kQKV;
    int b = row >> 10, s = row & 1023;
    int seg = c >> 10, cc = c & 1023;
    int h = cc >> 6, i = cc & 63;
    float x = qkv[idx];
    size_t dst = ((size_t)(b * kH + h) * kS + s) * kD + i;
    if (seg == 2) { v[dst] = x; return; }
    float sw  = qkv[(size_t)row * kQKV + (seg << 10) + (h << 6) + ((i + 32) & 63)];
    float val = ct[(s << 6) + i] * x + st[(s << 6) + i] * sw;
    (seg == 0 ? q : k)[dst] = val;
}

// causal softmax over scores rows; writes 0 beyond the diagonal
__global__ void softmax_k(float* __restrict__ sc)
{
    const int r = blockIdx.x;                 // kBH*kS rows
    const int s = r & (kS - 1);
    float* row = sc + (size_t)r * kS;
    const int n = s + 1;
    __shared__ float red[256];
    const int t = threadIdx.x;

    float m = -INFINITY;
    for (int i = t; i < n; i += 256) m = fmaxf(m, row[i]);
    red[t] = m; __syncthreads();
    for (int o = 128; o > 0; o >>= 1) {
        if (t < o) red[t] = fmaxf(red[t], red[t + o]);
        __syncthreads();
    }
    m = red[0]; __syncthreads();

    float sum = 0.f;
    for (int i = t; i < n; i += 256) { float e = expf(row[i] - m); row[i] = e; sum += e; }
    red[t] = sum; __syncthreads();
    for (int o = 128; o > 0; o >>= 1) {
        if (t < o) red[t] += red[t + o];
        __syncthreads();
    }
    float inv = 1.f / red[0];
    for (int i = t; i < n; i += 256) row[i] *= inv;
    for (int i = n + t; i < kS; i += 256) row[i] = 0.f;
}

// o [B,H,S,D] -> o2 [B,S,H*D]
__global__ void oresh_k(const float* __restrict__ o, float* __restrict__ o2)
{
    int idx = blockIdx.x * blockDim.x + threadIdx.x;   // kBH*kS*kD
    int bh  = idx / (kS * kD);
    int rem = idx % (kS * kD);
    int s = rem >> 6, d = rem & 63;
    int b = bh / kH, h = bh % kH;
    o2[((size_t)(b * kS + s) << 10) + (h << 6) + d] = o[idx];
}

__global__ void rmsnorm_k(const float* __restrict__ x, const float* __restrict__ w,
                          float* __restrict__ y)
{
    const int r = blockIdx.x;
    const float* xr = x + (size_t)r * kE;
    float* yr = y + (size_t)r * kE;
    __shared__ float red[256];
    const int t = threadIdx.x;
    float sum = 0.f;
    for (int i = t; i < kE; i += 256) { float v = xr[i]; sum += v * v; }
    red[t] = sum; __syncthreads();
    for (int o = 128; o > 0; o >>= 1) {
        if (t < o) red[t] += red[t + o];
        __syncthreads();
    }
    float rs = rsqrtf(red[0] / (float)kE + 1.1920929e-7f);
    for (int i = t; i < kE; i += 256) yr[i] = xr[i] * rs * w[i];
}

__global__ void elumul_k(float* __restrict__ u, const float* __restrict__ g)
{
    int i = blockIdx.x * blockDim.x + threadIdx.x;     // kBS*kF
    float gv = g[i];
    float e = gv > 0.f ? gv : expm1f(gv);
    u[i] *= e;
}

// ---------------------------------------------------------------------------
// Host launcher
// ---------------------------------------------------------------------------
extern "C" void kernel_launch(void* const* d_in, const int* in_sizes, int n_in,
                              void* d_out, int out_size)
{
    (void)in_sizes; (void)n_in; (void)out_size;
    const int*   tokens = (const int*)  d_in[0];
    const float* table  = (const float*)d_in[1];
    const float* Wq     = (const float*)d_in[2];
    const float* Wk     = (const float*)d_in[3];
    const float* Wv     = (const float*)d_in[4];
    const float* Wproj  = (const float*)d_in[5];
    const float* normw  = (const float*)d_in[6];
    const float* Wup    = (const float*)d_in[7];
    const float* Wgate  = (const float*)d_in[8];
    const float* Wdown  = (const float*)d_in[9];
    const float* predW  = (const float*)d_in[10];
    const float* predB  = (const float*)d_in[11];
    float* logits = (float*)d_out;

    float *emb, *hbuf, *qkv, *q, *kk, *vv, *sc, *o, *o2, *u, *g, *wt, *ct, *st;
    cudaGetSymbolAddress((void**)&emb,  g_emb);
    cudaGetSymbolAddress((void**)&hbuf, g_hbuf);
    cudaGetSymbolAddress((void**)&qkv,  g_qkv);
    cudaGetSymbolAddress((void**)&q,    g_q);
    cudaGetSymbolAddress((void**)&kk,   g_kk);
    cudaGetSymbolAddress((void**)&vv,   g_vv);
    cudaGetSymbolAddress((void**)&sc,   g_sc);
    cudaGetSymbolAddress((void**)&o,    g_o);
    cudaGetSymbolAddress((void**)&o2,   g_o2);
    cudaGetSymbolAddress((void**)&u,    g_u);
    cudaGetSymbolAddress((void**)&g,    g_g);
    cudaGetSymbolAddress((void**)&wt,   g_wt);
    cudaGetSymbolAddress((void**)&ct,   g_ct);
    cudaGetSymbolAddress((void**)&st,   g_st);

    const float inv_sqrt = 0.125f;   // 1/sqrt(64)

    embed_k <<<kBS * kE / 256, 256>>>(tokens, table, emb);
    costab_k<<<kS * kD / 256, 256>>>(ct, st);

    for (int l = 0; l < 4; l++) {
        const float* wq = Wq    + (size_t)l * kH * kE * kD;
        const float* wk = Wk    + (size_t)l * kH * kE * kD;
        const float* wv = Wv    + (size_t)l * kH * kE * kD;
        const float* wp = Wproj + (size_t)l * kE * kE;
        const float* nw = normw + (size_t)l * kE;
        const float* wu = Wup   + (size_t)l * kE * kF;
        const float* wg = Wgate + (size_t)l * kE * kF;
        const float* wd = Wdown + (size_t)l * kF * kE;

        // fused QKV weight transpose + one big GEMM  [2048,1024]x[1024,3072]
        wt_k<<<kE * kQKV / 256, 256>>>(wq, wk, wv, wt);
        gemm_k<128,128,16,8,8,false,false,false,false>
            <<<dim3(kQKV/128, kBS/128), 256>>>(emb, kE, 0, wt, kQKV, 0,
                                               qkv, kQKV, 0, nullptr, 1.f, kE);
        rope_k<<<kBS * kQKV / 256, 256>>>(qkv, ct, st, q, kk, vv);

        // scores = q @ k^T * inv_sqrt   (batched over (b,h), causal block-skip)
        gemm_k<128,128,16,8,8,true,false,false,true>
            <<<dim3(kS/128, kS/128, kBH), 256>>>(q, kD, (long long)kS*kD,
                                                 kk, kD, (long long)kS*kD,
                                                 sc, kS, (long long)kS*kS,
                                                 nullptr, inv_sqrt, kD);
        softmax_k<<<kBH * kS, 256>>>(sc);

        // o = attn @ v   [1024,1024]x[1024,64] per (b,h)
        gemm_k<128,64,16,8,4,false,false,false,false>
            <<<dim3(1, kS/128, kBH), 256>>>(sc, kS, (long long)kS*kS,
                                            vv, kD, (long long)kS*kD,
                                            o,  kD, (long long)kS*kD,
                                            nullptr, 1.f, kS);
        oresh_k<<<kBH * kS * kD / 256, 256>>>(o, o2);

        // emb += o2 @ Wproj
        gemm_k<128,128,16,8,8,false,true,false,false>
            <<<dim3(kE/128, kBS/128), 256>>>(o2, kE, 0, wp, kE, 0,
                                             emb, kE, 0, nullptr, 1.f, kE);

        // MLP
        rmsnorm_k<<<kBS, 256>>>(emb, nw, hbuf);
        gemm_k<128,128,16,8,8,false,false,false,false>
            <<<dim3(kF/128, kBS/128), 256>>>(hbuf, kE, 0, wu, kF, 0,
                                             u, kF, 0, nullptr, 1.f, kE);
        gemm_k<128,128,16,8,8,false,false,false,false>
            <<<dim3(kF/128, kBS/128), 256>>>(hbuf, kE, 0, wg, kF, 0,
                                             g, kF, 0, nullptr, 1.f, kE);
        elumul_k<<<kBS * kF / 256, 256>>>(u, g);
        gemm_k<128,128,16,8,8,false,true,false,false>
            <<<dim3(kE/128, kBS/128), 256>>>(u, kF, 0, wd, kE, 0,
                                             emb, kE, 0, nullptr, 1.f, kF);
    }

    // logits = emb @ pred_W + pred_b   [2048,1024]x[1024,32000]
    gemm_k<128,128,16,8,8,false,false,true,false>
        <<<dim3(kV/128, kBS/128), 256>>>(emb, kE, 0, predW, kV, 0,
                                         logits, kV, 0, predB, 1.f, kE);
}